// round 1
// baseline (speedup 1.0000x reference)
#include <cuda_runtime.h>
#include <math.h>

#define NN 16384
#define EE 524288
#define BB 8
#define FIN 26
#define DD 128
#define HH 256
#define LL 4
#define NRBF 16

// ---------------- device scratch (static, no allocs) ----------------
__device__ float g_h[NN * DD];
__device__ float g_Hs[NN * HH];
__device__ float g_Hd[NN * HH];
__device__ float g_S[NN * HH];
__device__ float g_u1[NN * HH];
__device__ float g_ef[EE * NRBF];
__device__ float g_dist[EE];
__device__ int   g_srcs[EE];
__device__ int   g_posmap[EE];
__device__ int   g_cnt[NN];
__device__ int   g_cur[NN];
__device__ int   g_offs[NN + 1];
__device__ float g_degf[NN];
__device__ float g_Wcbot[LL * HH * HH];   // W2 @ U1a per layer (256x256)
__device__ float g_b2u[LL * HH];          // b2 @ U1a per layer
__device__ float g_gsum[BB * DD];
__device__ float g_gcnt[BB];

__device__ __forceinline__ float silu_f(float x) {
    return x / (1.f + __expf(-x));
}

// ---------------- generic fp32 GEMM: C = act(A@B + bias + Cin + rowv*colv) ----
#define BM 64
#define BN 64
#define BK 16
__global__ void gemm_f32(const float* __restrict__ A, int lda,
                         const float* __restrict__ B, int ldb,
                         float* __restrict__ C, int ldc,
                         const float* __restrict__ Cin, int ldcin,
                         const float* __restrict__ bias,
                         const float* __restrict__ rowv,
                         const float* __restrict__ colv,
                         int M, int N, int K, int act)
{
    __shared__ float As[BK][BM];
    __shared__ float Bs[BK][BN];
    int tid = threadIdx.x;
    int bm = blockIdx.y * BM, bn = blockIdx.x * BN;
    int tx = tid % 16, ty = tid / 16;
    int ak = tid % 16, am = tid / 16;      // A tile load mapping
    int bnl = tid % 64, bkl = tid / 64;    // B tile load mapping
    float acc[4][4];
#pragma unroll
    for (int i = 0; i < 4; i++)
#pragma unroll
        for (int j = 0; j < 4; j++) acc[i][j] = 0.f;

    for (int k0 = 0; k0 < K; k0 += BK) {
#pragma unroll
        for (int i = 0; i < 4; i++) {
            int m = am + i * 16;
            As[ak][m] = (k0 + ak < K) ? A[(size_t)(bm + m) * lda + k0 + ak] : 0.f;
        }
#pragma unroll
        for (int i = 0; i < 4; i++) {
            int kk = bkl + i * 4;
            Bs[kk][bnl] = (k0 + kk < K) ? B[(size_t)(k0 + kk) * ldb + bn + bnl] : 0.f;
        }
        __syncthreads();
#pragma unroll
        for (int kk = 0; kk < BK; kk++) {
            float a[4], b[4];
#pragma unroll
            for (int i = 0; i < 4; i++) a[i] = As[kk][ty * 4 + i];
#pragma unroll
            for (int j = 0; j < 4; j++) b[j] = Bs[kk][tx * 4 + j];
#pragma unroll
            for (int i = 0; i < 4; i++)
#pragma unroll
                for (int j = 0; j < 4; j++) acc[i][j] += a[i] * b[j];
        }
        __syncthreads();
    }
#pragma unroll
    for (int i = 0; i < 4; i++) {
        int m = bm + ty * 4 + i;
#pragma unroll
        for (int j = 0; j < 4; j++) {
            int n = bn + tx * 4 + j;
            float v = acc[i][j];
            if (bias) v += bias[n];
            if (rowv) v += rowv[m] * colv[n];
            if (Cin)  v += Cin[(size_t)m * ldcin + n];
            if (act)  v = silu_f(v);
            C[(size_t)m * ldc + n] = v;
        }
    }
}

static void launch_gemm(const float* A, int lda, const float* B, int ldb,
                        float* C, int ldc, const float* Cin, int ldcin,
                        const float* bias, const float* rowv, const float* colv,
                        int M, int N, int K, int act)
{
    dim3 grid(N / BN, M / BM);
    gemm_f32<<<grid, 256>>>(A, lda, B, ldb, C, ldc, Cin, ldcin, bias, rowv, colv, M, N, K, act);
}

// ---------------- CSR build ----------------
__global__ void hist_kernel(const int* __restrict__ ei, int* __restrict__ cnt) {
    int e = blockIdx.x * blockDim.x + threadIdx.x;
    if (e >= EE) return;
    atomicAdd(&cnt[ei[EE + e]], 1);
}

__global__ void scan16k(const int* __restrict__ cnt, int* __restrict__ offs) {
    __shared__ int sh[1024];
    __shared__ int carry;
    int tid = threadIdx.x;
    if (tid == 0) carry = 0;
    __syncthreads();
    for (int ch = 0; ch < NN / 1024; ch++) {
        int i = ch * 1024 + tid;
        int v = cnt[i];
        sh[tid] = v;
        __syncthreads();
        for (int s = 1; s < 1024; s <<= 1) {
            int t = (tid >= s) ? sh[tid - s] : 0;
            __syncthreads();
            sh[tid] += t;
            __syncthreads();
        }
        offs[i] = carry + sh[tid] - v;
        int tot = sh[1023];
        __syncthreads();
        if (tid == 0) carry += tot;
        __syncthreads();
    }
    if (tid == 0) offs[NN] = carry;
}

__global__ void scatter_kernel(const int* __restrict__ ei, const int* __restrict__ offs,
                               int* __restrict__ cur, int* __restrict__ srcs,
                               int* __restrict__ posmap) {
    int e = blockIdx.x * blockDim.x + threadIdx.x;
    if (e >= EE) return;
    int d = ei[EE + e];
    int p = offs[d] + atomicAdd(&cur[d], 1);
    srcs[p] = ei[e];
    posmap[e] = p;
}

__global__ void degf_kernel(const int* __restrict__ offs, float* __restrict__ degf) {
    int n = blockIdx.x * blockDim.x + threadIdx.x;
    if (n >= NN) return;
    degf[n] = (float)(offs[n + 1] - offs[n]);
}

// ---------------- RBF (written in dst-sorted order) ----------------
__global__ void rbf_kernel(const float* __restrict__ pos, const int* __restrict__ ei,
                           const int* __restrict__ posmap,
                           float* __restrict__ ef, float* __restrict__ dsort) {
    int e = blockIdx.x * blockDim.x + threadIdx.x;
    if (e >= EE) return;
    int s = ei[e], d = ei[EE + e];
    float dx = pos[d * 3 + 0] - pos[s * 3 + 0];
    float dy = pos[d * 3 + 1] - pos[s * 3 + 1];
    float dz = pos[d * 3 + 2] - pos[s * 3 + 2];
    float dist = sqrtf(dx * dx + dy * dy + dz * dz + 1e-12f);
    int p = posmap[e];
    dsort[p] = dist;
    float env = (dist < 10.f) ? 0.5f * (cospif(dist * 0.1f) + 1.f) : 0.f;
    const float step = 10.f / 15.f;          // linspace(0,10,16)
    const float inv2w2 = -1.28f;             // -1/(2*(10/16)^2)
#pragma unroll
    for (int r = 0; r < NRBF; r++) {
        float diff = dist - r * step;
        ef[(size_t)p * NRBF + r] = env * expf(diff * diff * inv2w2);
    }
}

// ---------------- per-layer small precompute: b2 @ U1a ----------------
__global__ void b2u_kernel(const float* __restrict__ msg_b2,
                           const float* __restrict__ updW1,
                           float* __restrict__ b2u) {
    int l = blockIdx.x;
    int j = threadIdx.x;                       // 256
    const float* U1a = updW1 + (size_t)l * 2 * DD * HH + (size_t)DD * HH;
    const float* b2 = msg_b2 + (size_t)l * DD;
    float s = 0.f;
#pragma unroll 4
    for (int k = 0; k < DD; k++) s += b2[k] * U1a[(size_t)k * HH + j];
    b2u[l * HH + j] = s;
}

// ---------------- fused edge aggregation: S[n] = sum_e silu(Hs[src]+Hd[n]+ef@W1ef) ----
#define NPB 8
__global__ void edge_agg(const float* __restrict__ Hs, const float* __restrict__ Hd,
                         const float* __restrict__ W1ef,
                         const float* __restrict__ ef, const float* __restrict__ dsort,
                         const int* __restrict__ srcs, const int* __restrict__ offs,
                         float* __restrict__ S)
{
    __shared__ float wef[NRBF][HH];
    int c = threadIdx.x;   // 256 channels
#pragma unroll
    for (int r = 0; r < NRBF; r++) wef[r][c] = W1ef[r * HH + c];
    __syncthreads();
    int n0 = blockIdx.x * NPB;
    for (int q = 0; q < NPB; q++) {
        int n = n0 + q;
        float hd = Hd[(size_t)n * HH + c];
        float acc = 0.f;
        int p0 = offs[n], p1 = offs[n + 1];
        for (int p = p0; p < p1; p++) {
            int s = __ldg(&srcs[p]);
            float pre = __ldg(&Hs[(size_t)s * HH + c]) + hd;
            float dist = __ldg(&dsort[p]);
            if (dist < 10.f) {
#pragma unroll
                for (int r = 0; r < NRBF; r++)
                    pre += wef[r][c] * __ldg(&ef[(size_t)p * NRBF + r]);
            }
            acc += pre * (1.f / (1.f + __expf(-pre)));
        }
        S[(size_t)n * HH + c] = acc;
    }
}

// ---------------- readout ----------------
__global__ void graph_sum(const float* __restrict__ h, const int* __restrict__ batch,
                          float* __restrict__ gsum, float* __restrict__ gcnt) {
    int c = threadIdx.x;          // 128
    int base = blockIdx.x * 128;  // 128 nodes per block
    float acc = 0.f, cntl = 0.f;
    int curb = batch[base];
    for (int t = 0; t < 128; t++) {
        int n = base + t;
        int b = batch[n];
        if (b != curb) {
            atomicAdd(&gsum[curb * DD + c], acc);
            if (c == 0) atomicAdd(&gcnt[curb], cntl);
            acc = 0.f; cntl = 0.f; curb = b;
        }
        acc += h[(size_t)n * DD + c];
        cntl += 1.f;
    }
    atomicAdd(&gsum[curb * DD + c], acc);
    if (c == 0) atomicAdd(&gcnt[curb], cntl);
}

__global__ void readout_kernel(const float* __restrict__ gsum, const float* __restrict__ gcnt,
                               const float* __restrict__ rW1, const float* __restrict__ rb1,
                               const float* __restrict__ rW2, const float* __restrict__ rb2,
                               float* __restrict__ out) {
    __shared__ float g[BB * DD];
    __shared__ float t[BB * HH];
    int tid = threadIdx.x;  // 256
    for (int i = tid; i < BB * DD; i += 256) {
        int b = i / DD;
        g[i] = gsum[i] / fmaxf(gcnt[b], 1.f);
    }
    __syncthreads();
    int j = tid;  // hidden index
    for (int b = 0; b < BB; b++) {
        float s = rb1[j];
#pragma unroll 4
        for (int c = 0; c < DD; c++) s += g[b * DD + c] * rW1[(size_t)c * HH + j];
        t[b * HH + j] = silu_f(s);
    }
    __syncthreads();
    for (int o = tid; o < BB * 64; o += 256) {
        int b = o / 64, oc = o % 64;
        float s = rb2[oc];
#pragma unroll 4
        for (int jj = 0; jj < HH; jj++) s += t[b * HH + jj] * rW2[(size_t)jj * 64 + oc];
        out[o] = s;
    }
}

// ---------------- launch ----------------
extern "C" void kernel_launch(void* const* d_in, const int* in_sizes, int n_in,
                              void* d_out, int out_size)
{
    const float* positions     = (const float*)d_in[0];
    const float* node_features = (const float*)d_in[1];
    const int*   edge_index    = (const int*)  d_in[2];
    const int*   batch         = (const int*)  d_in[3];
    const float* emb_W1 = (const float*)d_in[4];
    const float* emb_b1 = (const float*)d_in[5];
    const float* emb_W2 = (const float*)d_in[6];
    const float* emb_b2 = (const float*)d_in[7];
    const float* msg_W1 = (const float*)d_in[8];
    const float* msg_b1 = (const float*)d_in[9];
    const float* msg_W2 = (const float*)d_in[10];
    const float* msg_b2 = (const float*)d_in[11];
    const float* upd_W1 = (const float*)d_in[12];
    const float* upd_b1 = (const float*)d_in[13];
    const float* upd_W2 = (const float*)d_in[14];
    const float* upd_b2 = (const float*)d_in[15];
    const float* r_W1   = (const float*)d_in[16];
    const float* r_b1   = (const float*)d_in[17];
    const float* r_W2   = (const float*)d_in[18];
    const float* r_b2   = (const float*)d_in[19];
    float* out = (float*)d_out;

    float *h, *Hs, *Hd, *S, *u1, *ef, *dsort, *degf, *Wcbot, *b2u, *gsum, *gcnt;
    int *srcs, *posmap, *cnt, *cur, *offs;
    cudaGetSymbolAddress((void**)&h,     g_h);
    cudaGetSymbolAddress((void**)&Hs,    g_Hs);
    cudaGetSymbolAddress((void**)&Hd,    g_Hd);
    cudaGetSymbolAddress((void**)&S,     g_S);
    cudaGetSymbolAddress((void**)&u1,    g_u1);
    cudaGetSymbolAddress((void**)&ef,    g_ef);
    cudaGetSymbolAddress((void**)&dsort, g_dist);
    cudaGetSymbolAddress((void**)&degf,  g_degf);
    cudaGetSymbolAddress((void**)&Wcbot, g_Wcbot);
    cudaGetSymbolAddress((void**)&b2u,   g_b2u);
    cudaGetSymbolAddress((void**)&gsum,  g_gsum);
    cudaGetSymbolAddress((void**)&gcnt,  g_gcnt);
    cudaGetSymbolAddress((void**)&srcs,  g_srcs);
    cudaGetSymbolAddress((void**)&posmap,g_posmap);
    cudaGetSymbolAddress((void**)&cnt,   g_cnt);
    cudaGetSymbolAddress((void**)&cur,   g_cur);
    cudaGetSymbolAddress((void**)&offs,  g_offs);

    cudaMemsetAsync(cnt, 0, NN * sizeof(int));
    cudaMemsetAsync(cur, 0, NN * sizeof(int));
    cudaMemsetAsync(gsum, 0, BB * DD * sizeof(float));
    cudaMemsetAsync(gcnt, 0, BB * sizeof(float));

    // CSR build by dst
    hist_kernel<<<EE / 256, 256>>>(edge_index, cnt);
    scan16k<<<1, 1024>>>(cnt, offs);
    scatter_kernel<<<EE / 256, 256>>>(edge_index, offs, cur, srcs, posmap);
    rbf_kernel<<<EE / 256, 256>>>(positions, edge_index, posmap, ef, dsort);
    degf_kernel<<<NN / 256, 256>>>(offs, degf);

    // per-layer fused weights: Wcbot = msg_W2 @ U1a  (256x128 @ 128x256)
    for (int l = 0; l < LL; l++) {
        const float* W2l  = msg_W2 + (size_t)l * HH * DD;
        const float* U1a  = upd_W1 + (size_t)l * 2 * DD * HH + (size_t)DD * HH;
        launch_gemm(W2l, DD, U1a, HH, Wcbot + (size_t)l * HH * HH, HH,
                    nullptr, 0, nullptr, nullptr, nullptr, HH, HH, DD, 0);
    }
    b2u_kernel<<<LL, HH>>>(msg_b2, upd_W1, b2u);

    // embedding: h = silu(nf@W1+b1)@W2 + b2   (t1 staged in Hs)
    launch_gemm(node_features, FIN, emb_W1, DD, Hs, DD,
                nullptr, 0, emb_b1, nullptr, nullptr, NN, DD, FIN, 1);
    launch_gemm(Hs, DD, emb_W2, DD, h, DD,
                nullptr, 0, emb_b2, nullptr, nullptr, NN, DD, DD, 0);

    for (int l = 0; l < LL; l++) {
        const float* W1l   = msg_W1 + (size_t)l * 272 * HH;
        const float* b1l   = msg_b1 + (size_t)l * HH;
        const float* U1h   = upd_W1 + (size_t)l * 2 * DD * HH;
        const float* ub1l  = upd_b1 + (size_t)l * HH;
        const float* uW2l  = upd_W2 + (size_t)l * HH * DD;
        const float* ub2l  = upd_b2 + (size_t)l * DD;

        // Hs = h @ W1[src rows],  Hd = h @ W1[dst rows] + b1
        launch_gemm(h, DD, W1l, HH, Hs, HH,
                    nullptr, 0, nullptr, nullptr, nullptr, NN, HH, DD, 0);
        launch_gemm(h, DD, W1l + (size_t)DD * HH, HH, Hd, HH,
                    nullptr, 0, b1l, nullptr, nullptr, NN, HH, DD, 0);

        // S[n] = sum over incoming edges of silu(pre)
        edge_agg<<<NN / NPB, HH>>>(Hs, Hd, W1l + (size_t)2 * DD * HH,
                                   ef, dsort, srcs, offs, S);

        // u1 = silu(h@U1h + S@Wcbot + ub1 + deg*b2u)
        launch_gemm(h, DD, U1h, HH, u1, HH,
                    nullptr, 0, nullptr, nullptr, nullptr, NN, HH, DD, 0);
        launch_gemm(S, HH, Wcbot + (size_t)l * HH * HH, HH, u1, HH,
                    u1, HH, ub1l, degf, b2u + (size_t)l * HH, NN, HH, HH, 1);

        // h = h + u1 @ updW2 + ub2
        launch_gemm(u1, HH, uW2l, DD, h, DD,
                    h, DD, ub2l, nullptr, nullptr, NN, DD, HH, 0);
    }

    graph_sum<<<NN / 128, 128>>>(h, batch, gsum, gcnt);
    readout_kernel<<<1, 256>>>(gsum, gcnt, r_W1, r_b1, r_W2, r_b2, out);
    (void)in_sizes; (void)n_in; (void)out_size;
}

// round 8
// speedup vs baseline: 2.0146x; 2.0146x over previous
#include <cuda_runtime.h>
#include <cstdint>
#include <math.h>

typedef unsigned int u32;

#define NN 16384
#define EE 524288
#define BB 8
#define FIN 26
#define DD 128
#define HH 256
#define LL 4
#define NRBF 16

// ---------------- device scratch (static, no allocs) ----------------
__device__ float g_h[NN * DD];
__device__ float g_HsHd[NN * 512];       // packed [Hs | Hd] per node
__device__ float g_S[NN * HH];
__device__ float g_u1[NN * HH];
__device__ float g_ef[EE * NRBF];
__device__ float g_dist[EE];
__device__ int   g_srcs[EE];
__device__ int   g_posmap[EE];
__device__ int   g_cnt[NN];
__device__ int   g_cur[NN];
__device__ int   g_offs[NN + 1];
__device__ float g_degf[NN];
__device__ float g_Bpack1[DD * 512];     // [W1src | W1dst] for current layer
__device__ float g_bias512[512];
__device__ float g_Bu[384 * HH];         // [U1h ; W2@U1a] for current layer
__device__ float g_b2u[LL * HH];         // b2 @ U1a per layer
__device__ float g_gsum[BB * DD];
__device__ float g_gcnt[BB];

__device__ __forceinline__ float silu_f(float x) {
    return x / (1.f + __expf(-x));
}

// =================== TF32 tensor-core GEMM (3xTF32 compensated) ===================
// C = act( [A1|A2] @ B + bias + rowv*colv + Cin )
// BM=128, BN=64, BK=32, 256 threads (warp grid 4x2), double-buffered cp.async.
#define TF_SMEM_BYTES 55296   // (2*128*36 + 2*32*72) * 4

__device__ __forceinline__ u32 f2tf(float x) {
    u32 r;
    asm("cvt.rna.tf32.f32 %0, %1;" : "=r"(r) : "f"(x));
    return r;
}

__device__ __forceinline__ void mma8(float* c, const u32* a, const u32 b0, const u32 b1) {
    asm volatile(
        "mma.sync.aligned.m16n8k8.row.col.f32.tf32.tf32.f32 "
        "{%0,%1,%2,%3},{%4,%5,%6,%7},{%8,%9},{%0,%1,%2,%3};"
        : "+f"(c[0]), "+f"(c[1]), "+f"(c[2]), "+f"(c[3])
        : "r"(a[0]), "r"(a[1]), "r"(a[2]), "r"(a[3]), "r"(b0), "r"(b1));
}

__device__ __forceinline__ void cpa16(u32 dst, const float* src) {
    asm volatile("cp.async.cg.shared.global [%0], [%1], 16;\n" :: "r"(dst), "l"(src));
}

__global__ void __launch_bounds__(256)
gemm_tf32(const float* __restrict__ A1, int lda1, int K1,
          const float* __restrict__ A2, int lda2,
          const float* __restrict__ B, int ldb,
          float* __restrict__ C, int ldc,
          const float* __restrict__ Cin, int ldcin,
          const float* __restrict__ bias,
          const float* __restrict__ rowv, const float* __restrict__ colv,
          int M, int N, int K, int act)
{
    extern __shared__ float sm[];
    float* As = sm;            // 2 buffers of [128][36]
    float* Bs = sm + 2 * 4608; // 2 buffers of [32][72]
    u32 sbase = (u32)__cvta_generic_to_shared(sm);

    int tid = threadIdx.x;
    int lane = tid & 31, warp = tid >> 5;
    int gid = lane >> 2, tig = lane & 3;
    int warp_m = (warp & 3) * 32, warp_n = (warp >> 2) * 32;
    int bm = blockIdx.y * 128, bn = blockIdx.x * 64;

    float acc[2][4][4];
#pragma unroll
    for (int mt = 0; mt < 2; mt++)
#pragma unroll
        for (int nt = 0; nt < 4; nt++)
#pragma unroll
            for (int i = 0; i < 4; i++) acc[mt][nt][i] = 0.f;

    int nchunks = K / 32;

    auto issue = [&](int t, int buf) {
        int k0 = t * 32;
        const float* Ap; int lda_, kloc;
        if (k0 < K1) { Ap = A1; lda_ = lda1; kloc = k0; }
        else         { Ap = A2; lda_ = lda2; kloc = k0 - K1; }
#pragma unroll
        for (int i = 0; i < 4; i++) {
            int slot = tid * 4 + i;
            int row = slot >> 3, col = (slot & 7) * 4;
            const float* src = Ap + (size_t)(bm + row) * lda_ + kloc + col;
            u32 dst = sbase + (u32)(buf * 4608 + row * 36 + col) * 4u;
            cpa16(dst, src);
        }
#pragma unroll
        for (int i = 0; i < 2; i++) {
            int slot = tid * 2 + i;
            int row = slot >> 4, col = (slot & 15) * 4;
            const float* src = B + (size_t)(k0 + row) * ldb + bn + col;
            u32 dst = sbase + (u32)(2 * 4608 + buf * 2304 + row * 72 + col) * 4u;
            cpa16(dst, src);
        }
        asm volatile("cp.async.commit_group;\n");
    };

    issue(0, 0);
    int buf = 0;
    for (int t = 0; t < nchunks; t++) {
        if (t + 1 < nchunks) {
            issue(t + 1, buf ^ 1);
            asm volatile("cp.async.wait_group 1;\n");
        } else {
            asm volatile("cp.async.wait_group 0;\n");
        }
        __syncthreads();

        const float* Ab = As + buf * 4608;
        const float* Bb = Bs + buf * 2304;
#pragma unroll
        for (int kk = 0; kk < 32; kk += 8) {
            u32 ahi[2][4], alo[2][4];
#pragma unroll
            for (int mt = 0; mt < 2; mt++) {
                int r = warp_m + mt * 16 + gid;
                float x0 = Ab[r * 36 + kk + tig];
                float x1 = Ab[(r + 8) * 36 + kk + tig];
                float x2 = Ab[r * 36 + kk + tig + 4];
                float x3 = Ab[(r + 8) * 36 + kk + tig + 4];
                ahi[mt][0] = f2tf(x0); alo[mt][0] = f2tf(x0 - __uint_as_float(ahi[mt][0]));
                ahi[mt][1] = f2tf(x1); alo[mt][1] = f2tf(x1 - __uint_as_float(ahi[mt][1]));
                ahi[mt][2] = f2tf(x2); alo[mt][2] = f2tf(x2 - __uint_as_float(ahi[mt][2]));
                ahi[mt][3] = f2tf(x3); alo[mt][3] = f2tf(x3 - __uint_as_float(ahi[mt][3]));
            }
#pragma unroll
            for (int nt = 0; nt < 4; nt++) {
                int cidx = warp_n + nt * 8 + gid;
                float y0 = Bb[(kk + tig) * 72 + cidx];
                float y1 = Bb[(kk + tig + 4) * 72 + cidx];
                u32 bhi0 = f2tf(y0), bhi1 = f2tf(y1);
                u32 blo0 = f2tf(y0 - __uint_as_float(bhi0));
                u32 blo1 = f2tf(y1 - __uint_as_float(bhi1));
#pragma unroll
                for (int mt = 0; mt < 2; mt++) {
                    mma8(acc[mt][nt], ahi[mt], bhi0, bhi1);
                    mma8(acc[mt][nt], ahi[mt], blo0, blo1);
                    mma8(acc[mt][nt], alo[mt], bhi0, bhi1);
                }
            }
        }
        __syncthreads();
        buf ^= 1;
    }

    // epilogue
#pragma unroll
    for (int mt = 0; mt < 2; mt++) {
#pragma unroll
        for (int nt = 0; nt < 4; nt++) {
            int r0 = bm + warp_m + mt * 16 + gid;
            int r1 = r0 + 8;
            int c0 = bn + warp_n + nt * 8 + tig * 2;
#pragma unroll
            for (int i = 0; i < 4; i++) {
                int r = (i < 2) ? r0 : r1;
                int c = c0 + (i & 1);
                float v = acc[mt][nt][i];
                if (bias) v += bias[c];
                if (rowv) v += rowv[r] * colv[c];
                if (Cin)  v += Cin[(size_t)r * ldcin + c];
                if (act)  v = silu_f(v);
                C[(size_t)r * ldc + c] = v;
            }
        }
    }
}

// =================== small SIMT GEMM (tiny K / weight precompute) ===================
#define BM 64
#define BN 64
#define BK 16
__global__ void gemm_f32(const float* __restrict__ A, int lda,
                         const float* __restrict__ B, int ldb,
                         float* __restrict__ C, int ldc,
                         const float* __restrict__ bias,
                         int M, int N, int K, int act)
{
    __shared__ float As[BK][BM];
    __shared__ float Bs[BK][BN];
    int tid = threadIdx.x;
    int bm = blockIdx.y * BM, bn = blockIdx.x * BN;
    int tx = tid % 16, ty = tid / 16;
    int ak = tid % 16, am = tid / 16;
    int bnl = tid % 64, bkl = tid / 64;
    float acc[4][4];
#pragma unroll
    for (int i = 0; i < 4; i++)
#pragma unroll
        for (int j = 0; j < 4; j++) acc[i][j] = 0.f;

    for (int k0 = 0; k0 < K; k0 += BK) {
#pragma unroll
        for (int i = 0; i < 4; i++) {
            int m = am + i * 16;
            As[ak][m] = (k0 + ak < K) ? A[(size_t)(bm + m) * lda + k0 + ak] : 0.f;
        }
#pragma unroll
        for (int i = 0; i < 4; i++) {
            int kk = bkl + i * 4;
            Bs[kk][bnl] = (k0 + kk < K) ? B[(size_t)(k0 + kk) * ldb + bn + bnl] : 0.f;
        }
        __syncthreads();
#pragma unroll
        for (int kk = 0; kk < BK; kk++) {
            float a[4], b[4];
#pragma unroll
            for (int i = 0; i < 4; i++) a[i] = As[kk][ty * 4 + i];
#pragma unroll
            for (int j = 0; j < 4; j++) b[j] = Bs[kk][tx * 4 + j];
#pragma unroll
            for (int i = 0; i < 4; i++)
#pragma unroll
                for (int j = 0; j < 4; j++) acc[i][j] += a[i] * b[j];
        }
        __syncthreads();
    }
#pragma unroll
    for (int i = 0; i < 4; i++) {
        int m = bm + ty * 4 + i;
#pragma unroll
        for (int j = 0; j < 4; j++) {
            int n = bn + tx * 4 + j;
            float v = acc[i][j];
            if (bias) v += bias[n];
            if (act)  v = silu_f(v);
            C[(size_t)m * ldc + n] = v;
        }
    }
}

// ---------------- CSR build ----------------
__global__ void hist_kernel(const int* __restrict__ ei, int* __restrict__ cnt) {
    int e = blockIdx.x * blockDim.x + threadIdx.x;
    if (e >= EE) return;
    atomicAdd(&cnt[ei[EE + e]], 1);
}

__global__ void scan16k(const int* __restrict__ cnt, int* __restrict__ offs) {
    __shared__ int sh[1024];
    __shared__ int carry;
    int tid = threadIdx.x;
    if (tid == 0) carry = 0;
    __syncthreads();
    for (int ch = 0; ch < NN / 1024; ch++) {
        int i = ch * 1024 + tid;
        int v = cnt[i];
        sh[tid] = v;
        __syncthreads();
        for (int s = 1; s < 1024; s <<= 1) {
            int t = (tid >= s) ? sh[tid - s] : 0;
            __syncthreads();
            sh[tid] += t;
            __syncthreads();
        }
        offs[i] = carry + sh[tid] - v;
        int tot = sh[1023];
        __syncthreads();
        if (tid == 0) carry += tot;
        __syncthreads();
    }
    if (tid == 0) offs[NN] = carry;
}

__global__ void scatter_kernel(const int* __restrict__ ei, const int* __restrict__ offs,
                               int* __restrict__ cur, int* __restrict__ srcs,
                               int* __restrict__ posmap) {
    int e = blockIdx.x * blockDim.x + threadIdx.x;
    if (e >= EE) return;
    int d = ei[EE + e];
    int p = offs[d] + atomicAdd(&cur[d], 1);
    srcs[p] = ei[e];
    posmap[e] = p;
}

__global__ void degf_kernel(const int* __restrict__ offs, float* __restrict__ degf) {
    int n = blockIdx.x * blockDim.x + threadIdx.x;
    if (n >= NN) return;
    degf[n] = (float)(offs[n + 1] - offs[n]);
}

// ---------------- RBF (written in dst-sorted order) ----------------
__global__ void rbf_kernel(const float* __restrict__ pos, const int* __restrict__ ei,
                           const int* __restrict__ posmap,
                           float* __restrict__ ef, float* __restrict__ dsort) {
    int e = blockIdx.x * blockDim.x + threadIdx.x;
    if (e >= EE) return;
    int s = ei[e], d = ei[EE + e];
    float dx = pos[d * 3 + 0] - pos[s * 3 + 0];
    float dy = pos[d * 3 + 1] - pos[s * 3 + 1];
    float dz = pos[d * 3 + 2] - pos[s * 3 + 2];
    float dist = sqrtf(dx * dx + dy * dy + dz * dz + 1e-12f);
    int p = posmap[e];
    dsort[p] = dist;
    float env = (dist < 10.f) ? 0.5f * (cospif(dist * 0.1f) + 1.f) : 0.f;
    const float step = 10.f / 15.f;
    const float inv2w2 = -1.28f;
#pragma unroll
    for (int r = 0; r < NRBF; r++) {
        float diff = dist - r * step;
        ef[(size_t)p * NRBF + r] = env * expf(diff * diff * inv2w2);
    }
}

// ---------------- per-layer packs ----------------
__global__ void b2u_kernel(const float* __restrict__ msg_b2,
                           const float* __restrict__ updW1,
                           float* __restrict__ b2u) {
    int l = blockIdx.x;
    int j = threadIdx.x;
    const float* U1a = updW1 + (size_t)l * 2 * DD * HH + (size_t)DD * HH;
    const float* b2 = msg_b2 + (size_t)l * DD;
    float s = 0.f;
#pragma unroll 4
    for (int k = 0; k < DD; k++) s += b2[k] * U1a[(size_t)k * HH + j];
    b2u[l * HH + j] = s;
}

__global__ void pack1_kernel(const float* __restrict__ W1l, float* __restrict__ Bpack1,
                             const float* __restrict__ b1l, float* __restrict__ bias512) {
    int idx = blockIdx.x * blockDim.x + threadIdx.x;
    if (idx < 512) bias512[idx] = (idx < 256) ? 0.f : b1l[idx - 256];
    if (idx >= DD * 512) return;
    int k = idx >> 9, j = idx & 511;
    Bpack1[idx] = (j < 256) ? W1l[k * 256 + j] : W1l[(128 + k) * 256 + (j - 256)];
}

__global__ void copyU1h_kernel(const float* __restrict__ U1h, float* __restrict__ Bu) {
    int idx = blockIdx.x * blockDim.x + threadIdx.x;
    if (idx < DD * HH) Bu[idx] = U1h[idx];
}

// ---------------- fused edge aggregation ----------------
#define NPB 8
__global__ void edge_agg(const float* __restrict__ HsHd,
                         const float* __restrict__ W1ef,
                         const float* __restrict__ ef, const float* __restrict__ dsort,
                         const int* __restrict__ srcs, const int* __restrict__ offs,
                         float* __restrict__ S)
{
    __shared__ float wef[NRBF][HH];
    int c = threadIdx.x;
#pragma unroll
    for (int r = 0; r < NRBF; r++) wef[r][c] = W1ef[r * HH + c];
    __syncthreads();
    int n0 = blockIdx.x * NPB;
    for (int q = 0; q < NPB; q++) {
        int n = n0 + q;
        float hd = HsHd[(size_t)n * 512 + 256 + c];
        float acc = 0.f;
        int p0 = offs[n], p1 = offs[n + 1];
        for (int p = p0; p < p1; p++) {
            int s = __ldg(&srcs[p]);
            float pre = __ldg(&HsHd[(size_t)s * 512 + c]) + hd;
            float dist = __ldg(&dsort[p]);
            if (dist < 10.f) {
#pragma unroll
                for (int r = 0; r < NRBF; r++)
                    pre += wef[r][c] * __ldg(&ef[(size_t)p * NRBF + r]);
            }
            acc += pre * (1.f / (1.f + __expf(-pre)));
        }
        S[(size_t)n * HH + c] = acc;
    }
}

// ---------------- readout ----------------
__global__ void graph_sum(const float* __restrict__ h, const int* __restrict__ batch,
                          float* __restrict__ gsum, float* __restrict__ gcnt) {
    int c = threadIdx.x;
    int base = blockIdx.x * 128;
    float acc = 0.f, cntl = 0.f;
    int curb = batch[base];
    for (int t = 0; t < 128; t++) {
        int n = base + t;
        int b = batch[n];
        if (b != curb) {
            atomicAdd(&gsum[curb * DD + c], acc);
            if (c == 0) atomicAdd(&gcnt[curb], cntl);
            acc = 0.f; cntl = 0.f; curb = b;
        }
        acc += h[(size_t)n * DD + c];
        cntl += 1.f;
    }
    atomicAdd(&gsum[curb * DD + c], acc);
    if (c == 0) atomicAdd(&gcnt[curb], cntl);
}

__global__ void readout_kernel(const float* __restrict__ gsum, const float* __restrict__ gcnt,
                               const float* __restrict__ rW1, const float* __restrict__ rb1,
                               const float* __restrict__ rW2, const float* __restrict__ rb2,
                               float* __restrict__ out) {
    __shared__ float g[BB * DD];
    __shared__ float t[BB * HH];
    int tid = threadIdx.x;
    for (int i = tid; i < BB * DD; i += 256) {
        int b = i / DD;
        g[i] = gsum[i] / fmaxf(gcnt[b], 1.f);
    }
    __syncthreads();
    int j = tid;
    for (int b = 0; b < BB; b++) {
        float s = rb1[j];
#pragma unroll 4
        for (int c = 0; c < DD; c++) s += g[b * DD + c] * rW1[(size_t)c * HH + j];
        t[b * HH + j] = silu_f(s);
    }
    __syncthreads();
    for (int o = tid; o < BB * 64; o += 256) {
        int b = o / 64, oc = o % 64;
        float s = rb2[oc];
#pragma unroll 4
        for (int jj = 0; jj < HH; jj++) s += t[b * HH + jj] * rW2[(size_t)jj * 64 + oc];
        out[o] = s;
    }
}

// ---------------- launch ----------------
static void launch_tf32(const float* A1, int lda1, int K1,
                        const float* A2, int lda2,
                        const float* B, int ldb,
                        float* C, int ldc, const float* Cin, int ldcin,
                        const float* bias, const float* rowv, const float* colv,
                        int M, int N, int K, int act)
{
    dim3 grid(N / 64, M / 128);
    gemm_tf32<<<grid, 256, TF_SMEM_BYTES>>>(A1, lda1, K1, A2, lda2, B, ldb,
                                            C, ldc, Cin, ldcin, bias, rowv, colv,
                                            M, N, K, act);
}

extern "C" void kernel_launch(void* const* d_in, const int* in_sizes, int n_in,
                              void* d_out, int out_size)
{
    const float* positions     = (const float*)d_in[0];
    const float* node_features = (const float*)d_in[1];
    const int*   edge_index    = (const int*)  d_in[2];
    const int*   batch         = (const int*)  d_in[3];
    const float* emb_W1 = (const float*)d_in[4];
    const float* emb_b1 = (const float*)d_in[5];
    const float* emb_W2 = (const float*)d_in[6];
    const float* emb_b2 = (const float*)d_in[7];
    const float* msg_W1 = (const float*)d_in[8];
    const float* msg_b1 = (const float*)d_in[9];
    const float* msg_W2 = (const float*)d_in[10];
    const float* msg_b2 = (const float*)d_in[11];
    const float* upd_W1 = (const float*)d_in[12];
    const float* upd_b1 = (const float*)d_in[13];
    const float* upd_W2 = (const float*)d_in[14];
    const float* upd_b2 = (const float*)d_in[15];
    const float* r_W1   = (const float*)d_in[16];
    const float* r_b1   = (const float*)d_in[17];
    const float* r_W2   = (const float*)d_in[18];
    const float* r_b2   = (const float*)d_in[19];
    float* out = (float*)d_out;

    float *h, *HsHd, *S, *u1, *ef, *dsort, *degf, *Bpack1, *bias512, *Bu, *b2u, *gsum, *gcnt;
    int *srcs, *posmap, *cnt, *cur, *offs;
    cudaGetSymbolAddress((void**)&h,      g_h);
    cudaGetSymbolAddress((void**)&HsHd,   g_HsHd);
    cudaGetSymbolAddress((void**)&S,      g_S);
    cudaGetSymbolAddress((void**)&u1,     g_u1);
    cudaGetSymbolAddress((void**)&ef,     g_ef);
    cudaGetSymbolAddress((void**)&dsort,  g_dist);
    cudaGetSymbolAddress((void**)&degf,   g_degf);
    cudaGetSymbolAddress((void**)&Bpack1, g_Bpack1);
    cudaGetSymbolAddress((void**)&bias512,g_bias512);
    cudaGetSymbolAddress((void**)&Bu,     g_Bu);
    cudaGetSymbolAddress((void**)&b2u,    g_b2u);
    cudaGetSymbolAddress((void**)&gsum,   g_gsum);
    cudaGetSymbolAddress((void**)&gcnt,   g_gcnt);
    cudaGetSymbolAddress((void**)&srcs,   g_srcs);
    cudaGetSymbolAddress((void**)&posmap, g_posmap);
    cudaGetSymbolAddress((void**)&cnt,    g_cnt);
    cudaGetSymbolAddress((void**)&cur,    g_cur);
    cudaGetSymbolAddress((void**)&offs,   g_offs);

    cudaFuncSetAttribute(gemm_tf32, cudaFuncAttributeMaxDynamicSharedMemorySize, TF_SMEM_BYTES);

    cudaMemsetAsync(cnt, 0, NN * sizeof(int));
    cudaMemsetAsync(cur, 0, NN * sizeof(int));
    cudaMemsetAsync(gsum, 0, BB * DD * sizeof(float));
    cudaMemsetAsync(gcnt, 0, BB * sizeof(float));

    // CSR build by dst
    hist_kernel<<<EE / 256, 256>>>(edge_index, cnt);
    scan16k<<<1, 1024>>>(cnt, offs);
    scatter_kernel<<<EE / 256, 256>>>(edge_index, offs, cur, srcs, posmap);
    rbf_kernel<<<EE / 256, 256>>>(positions, edge_index, posmap, ef, dsort);
    degf_kernel<<<NN / 256, 256>>>(offs, degf);

    b2u_kernel<<<LL, HH>>>(msg_b2, upd_W1, b2u);

    // embedding: t1 = silu(nf@W1+b1) (SIMT, K=26), h = t1@W2 + b2 (tf32)
    {
        dim3 g1(DD / 64, NN / 64);
        gemm_f32<<<g1, 256>>>(node_features, FIN, emb_W1, DD, u1, DD, emb_b1, NN, DD, FIN, 1);
    }
    launch_tf32(u1, DD, DD, nullptr, 0, emb_W2, DD, h, DD,
                nullptr, 0, emb_b2, nullptr, nullptr, NN, DD, DD, 0);

    for (int l = 0; l < LL; l++) {
        const float* W1l  = msg_W1 + (size_t)l * 272 * HH;
        const float* b1l  = msg_b1 + (size_t)l * HH;
        const float* W2l  = msg_W2 + (size_t)l * HH * DD;
        const float* U1h  = upd_W1 + (size_t)l * 2 * DD * HH;
        const float* U1a  = U1h + (size_t)DD * HH;
        const float* ub1l = upd_b1 + (size_t)l * HH;
        const float* uW2l = upd_W2 + (size_t)l * HH * DD;
        const float* ub2l = upd_b2 + (size_t)l * DD;

        // packs: Bpack1 = [W1src | W1dst], bias512 = [0 | b1]
        pack1_kernel<<<(DD * 512) / 256, 256>>>(W1l, Bpack1, b1l, bias512);
        // Bu = [U1h ; W2l @ U1a]
        copyU1h_kernel<<<(DD * HH) / 256, 256>>>(U1h, Bu);
        {
            dim3 gw(HH / 64, HH / 64);
            gemm_f32<<<gw, 256>>>(W2l, DD, U1a, HH, Bu + (size_t)DD * HH, HH,
                                  nullptr, HH, HH, DD, 0);
        }

        // HsHd = h @ Bpack1 + bias512   (N x 512)
        launch_tf32(h, DD, DD, nullptr, 0, Bpack1, 512, HsHd, 512,
                    nullptr, 0, bias512, nullptr, nullptr, NN, 512, DD, 0);

        // S[n] = sum over incoming edges of silu(pre)
        edge_agg<<<NN / NPB, HH>>>(HsHd, W1l + (size_t)2 * DD * HH,
                                   ef, dsort, srcs, offs, S);

        // u1 = silu([h|S] @ Bu + ub1 + deg*b2u)
        launch_tf32(h, DD, DD, S, HH, Bu, HH, u1, HH,
                    nullptr, 0, ub1l, degf, b2u + (size_t)l * HH, NN, HH, 384, 1);

        // h = h + u1 @ uW2 + ub2
        launch_tf32(u1, HH, HH, nullptr, 0, uW2l, DD, h, DD,
                    h, DD, ub2l, nullptr, nullptr, NN, DD, HH, 0);
    }

    graph_sum<<<NN / 128, 128>>>(h, batch, gsum, gcnt);
    readout_kernel<<<1, 256>>>(gsum, gcnt, r_W1, r_b1, r_W2, r_b2, out);
    (void)in_sizes; (void)n_in; (void)out_size;
}

// round 13
// speedup vs baseline: 2.0392x; 1.0122x over previous
#include <cuda_runtime.h>
#include <cstdint>
#include <math.h>

typedef unsigned int u32;

#define NN 16384
#define EE 524288
#define BB 8
#define FIN 26
#define DD 128
#define HH 256
#define LL 4
#define NRBF 16

// ---------------- device scratch (static, no allocs) ----------------
__device__ float g_h[NN * DD];
__device__ float g_HsHd[NN * 512];       // packed [Hs | Hd] per node
__device__ float g_S[NN * HH];
__device__ float g_u1[NN * HH];
__device__ float g_ef[EE * NRBF];
__device__ float g_dist[EE];
__device__ int   g_srcs[EE];
__device__ int   g_posmap[EE];
__device__ int   g_cnt[NN];
__device__ int   g_cur[NN];
__device__ int   g_offs[NN + 1];
__device__ float g_degf[NN];
__device__ float g_bias512[512];
__device__ float g_Bu[384 * HH];         // fp32 staging for [U1h ; W2@U1a]
__device__ float g_b2u[LL * HH];         // b2 @ U1a per layer
__device__ float g_gsum[BB * DD];
__device__ float g_gcnt[BB];
// precomputed TF32 hi/lo weight splits (current layer)
__device__ float g_p1hi[DD * 512];
__device__ float g_p1lo[DD * 512];
__device__ float g_buhi[384 * HH];
__device__ float g_bulo[384 * HH];
__device__ float g_w2hi[HH * DD];
__device__ float g_w2lo[HH * DD];

__device__ __forceinline__ float silu_f(float x) {
    return x / (1.f + __expf(-x));
}

__device__ __forceinline__ u32 f2tf(float x) {
    u32 r;
    asm("cvt.rna.tf32.f32 %0, %1;" : "=r"(r) : "f"(x));
    return r;
}

// =================== TF32 tensor-core GEMM (3xTF32, B pre-split) ===================
// C = act( [A1|A2] @ B + bias + rowv*colv + Cin ), B given as hi/lo tf32 floats.
// BM=128, BN=64, BK=32, 256 threads, double-buffered cp.async.
// smem: A 2x[128][36] @0, Bhi 2x[32][72] @9216, Blo 2x[32][72] @13824  (73728 B)
#define TF_SMEM_BYTES 73728

__device__ __forceinline__ void mma8(float* c, const u32* a, const u32 b0, const u32 b1) {
    asm volatile(
        "mma.sync.aligned.m16n8k8.row.col.f32.tf32.tf32.f32 "
        "{%0,%1,%2,%3},{%4,%5,%6,%7},{%8,%9},{%0,%1,%2,%3};"
        : "+f"(c[0]), "+f"(c[1]), "+f"(c[2]), "+f"(c[3])
        : "r"(a[0]), "r"(a[1]), "r"(a[2]), "r"(a[3]), "r"(b0), "r"(b1));
}

__device__ __forceinline__ void cpa16(u32 dst, const float* src) {
    asm volatile("cp.async.cg.shared.global [%0], [%1], 16;\n" :: "r"(dst), "l"(src));
}

__global__ void __launch_bounds__(256)
gemm_tf32(const float* __restrict__ A1, int lda1, int K1,
          const float* __restrict__ A2, int lda2,
          const float* __restrict__ Bhi, const float* __restrict__ Blo, int ldb,
          float* __restrict__ C, int ldc,
          const float* __restrict__ Cin, int ldcin,
          const float* __restrict__ bias,
          const float* __restrict__ rowv, const float* __restrict__ colv,
          int M, int N, int K, int act)
{
    extern __shared__ float sm[];
    u32 sbase = (u32)__cvta_generic_to_shared(sm);

    int tid = threadIdx.x;
    int lane = tid & 31, warp = tid >> 5;
    int gid = lane >> 2, tig = lane & 3;
    int warp_m = (warp & 3) * 32, warp_n = (warp >> 2) * 32;
    int bm = blockIdx.y * 128, bn = blockIdx.x * 64;

    float acc[2][4][4];
#pragma unroll
    for (int mt = 0; mt < 2; mt++)
#pragma unroll
        for (int nt = 0; nt < 4; nt++)
#pragma unroll
            for (int i = 0; i < 4; i++) acc[mt][nt][i] = 0.f;

    int nchunks = K / 32;

    auto issue = [&](int t, int buf) {
        int k0 = t * 32;
        const float* Ap; int lda_, kloc;
        if (k0 < K1) { Ap = A1; lda_ = lda1; kloc = k0; }
        else         { Ap = A2; lda_ = lda2; kloc = k0 - K1; }
#pragma unroll
        for (int i = 0; i < 4; i++) {
            int slot = tid * 4 + i;
            int row = slot >> 3, col = (slot & 7) * 4;
            const float* src = Ap + (size_t)(bm + row) * lda_ + kloc + col;
            u32 dst = sbase + (u32)(buf * 4608 + row * 36 + col) * 4u;
            cpa16(dst, src);
        }
#pragma unroll
        for (int i = 0; i < 2; i++) {
            int slot = tid * 2 + i;
            int row = slot >> 4, col = (slot & 15) * 4;
            size_t gof = (size_t)(k0 + row) * ldb + bn + col;
            u32 sof = (u32)(buf * 2304 + row * 72 + col) * 4u;
            cpa16(sbase + 9216u * 4u + sof, Bhi + gof);
            cpa16(sbase + 13824u * 4u + sof, Blo + gof);
        }
        asm volatile("cp.async.commit_group;\n");
    };

    issue(0, 0);
    int buf = 0;
    for (int t = 0; t < nchunks; t++) {
        if (t + 1 < nchunks) {
            issue(t + 1, buf ^ 1);
            asm volatile("cp.async.wait_group 1;\n");
        } else {
            asm volatile("cp.async.wait_group 0;\n");
        }
        __syncthreads();

        const float* Ab = sm + buf * 4608;
        const float* Bh = sm + 9216 + buf * 2304;
        const float* Bl = sm + 13824 + buf * 2304;
#pragma unroll
        for (int kk = 0; kk < 32; kk += 8) {
            u32 ahi[2][4], alo[2][4];
#pragma unroll
            for (int mt = 0; mt < 2; mt++) {
                int r = warp_m + mt * 16 + gid;
                float x0 = Ab[r * 36 + kk + tig];
                float x1 = Ab[(r + 8) * 36 + kk + tig];
                float x2 = Ab[r * 36 + kk + tig + 4];
                float x3 = Ab[(r + 8) * 36 + kk + tig + 4];
                ahi[mt][0] = f2tf(x0); alo[mt][0] = f2tf(x0 - __uint_as_float(ahi[mt][0]));
                ahi[mt][1] = f2tf(x1); alo[mt][1] = f2tf(x1 - __uint_as_float(ahi[mt][1]));
                ahi[mt][2] = f2tf(x2); alo[mt][2] = f2tf(x2 - __uint_as_float(ahi[mt][2]));
                ahi[mt][3] = f2tf(x3); alo[mt][3] = f2tf(x3 - __uint_as_float(ahi[mt][3]));
            }
#pragma unroll
            for (int nt = 0; nt < 4; nt++) {
                int cidx = warp_n + nt * 8 + gid;
                u32 bh0 = __float_as_uint(Bh[(kk + tig) * 72 + cidx]);
                u32 bh1 = __float_as_uint(Bh[(kk + tig + 4) * 72 + cidx]);
                u32 bl0 = __float_as_uint(Bl[(kk + tig) * 72 + cidx]);
                u32 bl1 = __float_as_uint(Bl[(kk + tig + 4) * 72 + cidx]);
#pragma unroll
                for (int mt = 0; mt < 2; mt++) {
                    mma8(acc[mt][nt], ahi[mt], bh0, bh1);
                    mma8(acc[mt][nt], ahi[mt], bl0, bl1);
                    mma8(acc[mt][nt], alo[mt], bh0, bh1);
                }
            }
        }
        __syncthreads();
        buf ^= 1;
    }

    // epilogue
#pragma unroll
    for (int mt = 0; mt < 2; mt++) {
#pragma unroll
        for (int nt = 0; nt < 4; nt++) {
            int r0 = bm + warp_m + mt * 16 + gid;
            int r1 = r0 + 8;
            int c0 = bn + warp_n + nt * 8 + tig * 2;
#pragma unroll
            for (int i = 0; i < 4; i++) {
                int r = (i < 2) ? r0 : r1;
                int c = c0 + (i & 1);
                float v = acc[mt][nt][i];
                if (bias) v += bias[c];
                if (rowv) v += rowv[r] * colv[c];
                if (Cin)  v += Cin[(size_t)r * ldcin + c];
                if (act)  v = silu_f(v);
                C[(size_t)r * ldc + c] = v;
            }
        }
    }
}

// =================== small SIMT GEMM (tiny K / weight precompute) ===================
#define BM 64
#define BN 64
#define BK 16
__global__ void gemm_f32(const float* __restrict__ A, int lda,
                         const float* __restrict__ B, int ldb,
                         float* __restrict__ C, int ldc,
                         const float* __restrict__ bias,
                         int M, int N, int K, int act)
{
    __shared__ float As[BK][BM];
    __shared__ float Bs[BK][BN];
    int tid = threadIdx.x;
    int bm = blockIdx.y * BM, bn = blockIdx.x * BN;
    int tx = tid % 16, ty = tid / 16;
    int ak = tid % 16, am = tid / 16;
    int bnl = tid % 64, bkl = tid / 64;
    float acc[4][4];
#pragma unroll
    for (int i = 0; i < 4; i++)
#pragma unroll
        for (int j = 0; j < 4; j++) acc[i][j] = 0.f;

    for (int k0 = 0; k0 < K; k0 += BK) {
#pragma unroll
        for (int i = 0; i < 4; i++) {
            int m = am + i * 16;
            As[ak][m] = (k0 + ak < K) ? A[(size_t)(bm + m) * lda + k0 + ak] : 0.f;
        }
#pragma unroll
        for (int i = 0; i < 4; i++) {
            int kk = bkl + i * 4;
            Bs[kk][bnl] = (k0 + kk < K) ? B[(size_t)(k0 + kk) * ldb + bn + bnl] : 0.f;
        }
        __syncthreads();
#pragma unroll
        for (int kk = 0; kk < BK; kk++) {
            float a[4], b[4];
#pragma unroll
            for (int i = 0; i < 4; i++) a[i] = As[kk][ty * 4 + i];
#pragma unroll
            for (int j = 0; j < 4; j++) b[j] = Bs[kk][tx * 4 + j];
#pragma unroll
            for (int i = 0; i < 4; i++)
#pragma unroll
                for (int j = 0; j < 4; j++) acc[i][j] += a[i] * b[j];
        }
        __syncthreads();
    }
#pragma unroll
    for (int i = 0; i < 4; i++) {
        int m = bm + ty * 4 + i;
#pragma unroll
        for (int j = 0; j < 4; j++) {
            int n = bn + tx * 4 + j;
            float v = acc[i][j];
            if (bias) v += bias[n];
            if (act)  v = silu_f(v);
            C[(size_t)m * ldc + n] = v;
        }
    }
}

// ---------------- CSR build ----------------
__global__ void hist_kernel(const int* __restrict__ ei, int* __restrict__ cnt) {
    int e = blockIdx.x * blockDim.x + threadIdx.x;
    if (e >= EE) return;
    atomicAdd(&cnt[ei[EE + e]], 1);
}

__global__ void scan16k(const int* __restrict__ cnt, int* __restrict__ offs) {
    __shared__ int sh[1024];
    __shared__ int carry;
    int tid = threadIdx.x;
    if (tid == 0) carry = 0;
    __syncthreads();
    for (int ch = 0; ch < NN / 1024; ch++) {
        int i = ch * 1024 + tid;
        int v = cnt[i];
        sh[tid] = v;
        __syncthreads();
        for (int s = 1; s < 1024; s <<= 1) {
            int t = (tid >= s) ? sh[tid - s] : 0;
            __syncthreads();
            sh[tid] += t;
            __syncthreads();
        }
        offs[i] = carry + sh[tid] - v;
        int tot = sh[1023];
        __syncthreads();
        if (tid == 0) carry += tot;
        __syncthreads();
    }
    if (tid == 0) offs[NN] = carry;
}

__global__ void scatter_kernel(const int* __restrict__ ei, const int* __restrict__ offs,
                               int* __restrict__ cur, int* __restrict__ srcs,
                               int* __restrict__ posmap) {
    int e = blockIdx.x * blockDim.x + threadIdx.x;
    if (e >= EE) return;
    int d = ei[EE + e];
    int p = offs[d] + atomicAdd(&cur[d], 1);
    srcs[p] = ei[e];
    posmap[e] = p;
}

__global__ void degf_kernel(const int* __restrict__ offs, float* __restrict__ degf) {
    int n = blockIdx.x * blockDim.x + threadIdx.x;
    if (n >= NN) return;
    degf[n] = (float)(offs[n + 1] - offs[n]);
}

// ---------------- RBF (written in dst-sorted order; far edges skip ef store) ----------------
__global__ void rbf_kernel(const float* __restrict__ pos, const int* __restrict__ ei,
                           const int* __restrict__ posmap,
                           float* __restrict__ ef, float* __restrict__ dsort) {
    int e = blockIdx.x * blockDim.x + threadIdx.x;
    if (e >= EE) return;
    int s = ei[e], d = ei[EE + e];
    float dx = pos[d * 3 + 0] - pos[s * 3 + 0];
    float dy = pos[d * 3 + 1] - pos[s * 3 + 1];
    float dz = pos[d * 3 + 2] - pos[s * 3 + 2];
    float dist = sqrtf(dx * dx + dy * dy + dz * dz + 1e-12f);
    int p = posmap[e];
    dsort[p] = dist;
    if (dist < 10.f) {
        float env = 0.5f * (cospif(dist * 0.1f) + 1.f);
        const float step = 10.f / 15.f;
        const float inv2w2 = -1.28f;
#pragma unroll
        for (int r = 0; r < NRBF; r++) {
            float diff = dist - r * step;
            ef[(size_t)p * NRBF + r] = env * expf(diff * diff * inv2w2);
        }
    }
}

// ---------------- per-layer packs ----------------
__global__ void b2u_kernel(const float* __restrict__ msg_b2,
                           const float* __restrict__ updW1,
                           float* __restrict__ b2u) {
    int l = blockIdx.x;
    int j = threadIdx.x;
    const float* U1a = updW1 + (size_t)l * 2 * DD * HH + (size_t)DD * HH;
    const float* b2 = msg_b2 + (size_t)l * DD;
    float s = 0.f;
#pragma unroll 4
    for (int k = 0; k < DD; k++) s += b2[k] * U1a[(size_t)k * HH + j];
    b2u[l * HH + j] = s;
}

// pack + split in one pass: Bpack1 = [W1src | W1dst] split to hi/lo; bias512
__global__ void pack1_split_kernel(const float* __restrict__ W1l,
                                   float* __restrict__ p1hi, float* __restrict__ p1lo,
                                   const float* __restrict__ b1l, float* __restrict__ bias512) {
    int idx = blockIdx.x * blockDim.x + threadIdx.x;
    if (idx < 512) bias512[idx] = (idx < 256) ? 0.f : b1l[idx - 256];
    if (idx >= DD * 512) return;
    int k = idx >> 9, j = idx & 511;
    float v = (j < 256) ? W1l[k * 256 + j] : W1l[(128 + k) * 256 + (j - 256)];
    u32 hi = f2tf(v);
    p1hi[idx] = __uint_as_float(hi);
    p1lo[idx] = __uint_as_float(f2tf(v - __uint_as_float(hi)));
}

__global__ void copyU1h_kernel(const float* __restrict__ U1h, float* __restrict__ Bu) {
    int idx = blockIdx.x * blockDim.x + threadIdx.x;
    if (idx < DD * HH) Bu[idx] = U1h[idx];
}

// generic tf32 split: hi/lo from src, n elements
__global__ void split_kernel(const float* __restrict__ src,
                             float* __restrict__ hi, float* __restrict__ lo, int n) {
    int idx = blockIdx.x * blockDim.x + threadIdx.x;
    if (idx >= n) return;
    float v = src[idx];
    u32 h = f2tf(v);
    hi[idx] = __uint_as_float(h);
    lo[idx] = __uint_as_float(f2tf(v - __uint_as_float(h)));
}

// ---------------- fused edge aggregation ----------------
#define NPB 8
__global__ void edge_agg(const float* __restrict__ HsHd,
                         const float* __restrict__ W1ef,
                         const float* __restrict__ ef, const float* __restrict__ dsort,
                         const int* __restrict__ srcs, const int* __restrict__ offs,
                         float* __restrict__ S)
{
    __shared__ float wef[NRBF][HH];
    int c = threadIdx.x;
#pragma unroll
    for (int r = 0; r < NRBF; r++) wef[r][c] = W1ef[r * HH + c];
    __syncthreads();
    int n0 = blockIdx.x * NPB;
    for (int q = 0; q < NPB; q++) {
        int n = n0 + q;
        float hd = HsHd[(size_t)n * 512 + 256 + c];
        float acc = 0.f;
        int p0 = offs[n], p1 = offs[n + 1];
        for (int p = p0; p < p1; p++) {
            int s = __ldg(&srcs[p]);
            float pre = __ldg(&HsHd[(size_t)s * 512 + c]) + hd;
            float dist = __ldg(&dsort[p]);
            if (dist < 10.f) {
#pragma unroll
                for (int r = 0; r < NRBF; r++)
                    pre += wef[r][c] * __ldg(&ef[(size_t)p * NRBF + r]);
            }
            acc += pre * (1.f / (1.f + __expf(-pre)));
        }
        S[(size_t)n * HH + c] = acc;
    }
}

// ---------------- readout ----------------
__global__ void graph_sum(const float* __restrict__ h, const int* __restrict__ batch,
                          float* __restrict__ gsum, float* __restrict__ gcnt) {
    int c = threadIdx.x;
    int base = blockIdx.x * 128;
    float acc = 0.f, cntl = 0.f;
    int curb = batch[base];
    for (int t = 0; t < 128; t++) {
        int n = base + t;
        int b = batch[n];
        if (b != curb) {
            atomicAdd(&gsum[curb * DD + c], acc);
            if (c == 0) atomicAdd(&gcnt[curb], cntl);
            acc = 0.f; cntl = 0.f; curb = b;
        }
        acc += h[(size_t)n * DD + c];
        cntl += 1.f;
    }
    atomicAdd(&gsum[curb * DD + c], acc);
    if (c == 0) atomicAdd(&gcnt[curb], cntl);
}

__global__ void readout_kernel(const float* __restrict__ gsum, const float* __restrict__ gcnt,
                               const float* __restrict__ rW1, const float* __restrict__ rb1,
                               const float* __restrict__ rW2, const float* __restrict__ rb2,
                               float* __restrict__ out) {
    __shared__ float g[BB * DD];
    __shared__ float t[BB * HH];
    int tid = threadIdx.x;
    for (int i = tid; i < BB * DD; i += 256) {
        int b = i / DD;
        g[i] = gsum[i] / fmaxf(gcnt[b], 1.f);
    }
    __syncthreads();
    int j = tid;
    for (int b = 0; b < BB; b++) {
        float s = rb1[j];
#pragma unroll 4
        for (int c = 0; c < DD; c++) s += g[b * DD + c] * rW1[(size_t)c * HH + j];
        t[b * HH + j] = silu_f(s);
    }
    __syncthreads();
    for (int o = tid; o < BB * 64; o += 256) {
        int b = o / 64, oc = o % 64;
        float s = rb2[oc];
#pragma unroll 4
        for (int jj = 0; jj < HH; jj++) s += t[b * HH + jj] * rW2[(size_t)jj * 64 + oc];
        out[o] = s;
    }
}

// ---------------- launch ----------------
static void launch_tf32(const float* A1, int lda1, int K1,
                        const float* A2, int lda2,
                        const float* Bhi, const float* Blo, int ldb,
                        float* C, int ldc, const float* Cin, int ldcin,
                        const float* bias, const float* rowv, const float* colv,
                        int M, int N, int K, int act)
{
    dim3 grid(N / 64, M / 128);
    gemm_tf32<<<grid, 256, TF_SMEM_BYTES>>>(A1, lda1, K1, A2, lda2, Bhi, Blo, ldb,
                                            C, ldc, Cin, ldcin, bias, rowv, colv,
                                            M, N, K, act);
}

extern "C" void kernel_launch(void* const* d_in, const int* in_sizes, int n_in,
                              void* d_out, int out_size)
{
    const float* positions     = (const float*)d_in[0];
    const float* node_features = (const float*)d_in[1];
    const int*   edge_index    = (const int*)  d_in[2];
    const int*   batch         = (const int*)  d_in[3];
    const float* emb_W1 = (const float*)d_in[4];
    const float* emb_b1 = (const float*)d_in[5];
    const float* emb_W2 = (const float*)d_in[6];
    const float* emb_b2 = (const float*)d_in[7];
    const float* msg_W1 = (const float*)d_in[8];
    const float* msg_b1 = (const float*)d_in[9];
    const float* msg_W2 = (const float*)d_in[10];
    const float* msg_b2 = (const float*)d_in[11];
    const float* upd_W1 = (const float*)d_in[12];
    const float* upd_b1 = (const float*)d_in[13];
    const float* upd_W2 = (const float*)d_in[14];
    const float* upd_b2 = (const float*)d_in[15];
    const float* r_W1   = (const float*)d_in[16];
    const float* r_b1   = (const float*)d_in[17];
    const float* r_W2   = (const float*)d_in[18];
    const float* r_b2   = (const float*)d_in[19];
    float* out = (float*)d_out;

    float *h, *HsHd, *S, *u1, *ef, *dsort, *degf, *bias512, *Bu, *b2u, *gsum, *gcnt;
    float *p1hi, *p1lo, *buhi, *bulo, *w2hi, *w2lo;
    int *srcs, *posmap, *cnt, *cur, *offs;
    cudaGetSymbolAddress((void**)&h,      g_h);
    cudaGetSymbolAddress((void**)&HsHd,   g_HsHd);
    cudaGetSymbolAddress((void**)&S,      g_S);
    cudaGetSymbolAddress((void**)&u1,     g_u1);
    cudaGetSymbolAddress((void**)&ef,     g_ef);
    cudaGetSymbolAddress((void**)&dsort,  g_dist);
    cudaGetSymbolAddress((void**)&degf,   g_degf);
    cudaGetSymbolAddress((void**)&bias512,g_bias512);
    cudaGetSymbolAddress((void**)&Bu,     g_Bu);
    cudaGetSymbolAddress((void**)&b2u,    g_b2u);
    cudaGetSymbolAddress((void**)&gsum,   g_gsum);
    cudaGetSymbolAddress((void**)&gcnt,   g_gcnt);
    cudaGetSymbolAddress((void**)&p1hi,   g_p1hi);
    cudaGetSymbolAddress((void**)&p1lo,   g_p1lo);
    cudaGetSymbolAddress((void**)&buhi,   g_buhi);
    cudaGetSymbolAddress((void**)&bulo,   g_bulo);
    cudaGetSymbolAddress((void**)&w2hi,   g_w2hi);
    cudaGetSymbolAddress((void**)&w2lo,   g_w2lo);
    cudaGetSymbolAddress((void**)&srcs,   g_srcs);
    cudaGetSymbolAddress((void**)&posmap, g_posmap);
    cudaGetSymbolAddress((void**)&cnt,    g_cnt);
    cudaGetSymbolAddress((void**)&cur,    g_cur);
    cudaGetSymbolAddress((void**)&offs,   g_offs);

    cudaFuncSetAttribute(gemm_tf32, cudaFuncAttributeMaxDynamicSharedMemorySize, TF_SMEM_BYTES);

    cudaMemsetAsync(cnt, 0, NN * sizeof(int));
    cudaMemsetAsync(cur, 0, NN * sizeof(int));
    cudaMemsetAsync(gsum, 0, BB * DD * sizeof(float));
    cudaMemsetAsync(gcnt, 0, BB * sizeof(float));

    // CSR build by dst
    hist_kernel<<<EE / 256, 256>>>(edge_index, cnt);
    scan16k<<<1, 1024>>>(cnt, offs);
    scatter_kernel<<<EE / 256, 256>>>(edge_index, offs, cur, srcs, posmap);
    rbf_kernel<<<EE / 256, 256>>>(positions, edge_index, posmap, ef, dsort);
    degf_kernel<<<NN / 256, 256>>>(offs, degf);

    b2u_kernel<<<LL, HH>>>(msg_b2, upd_W1, b2u);

    // embedding: t1 = silu(nf@W1+b1) (SIMT, K=26), h = t1@W2 + b2 (tf32)
    {
        dim3 g1(DD / 64, NN / 64);
        gemm_f32<<<g1, 256>>>(node_features, FIN, emb_W1, DD, u1, DD, emb_b1, NN, DD, FIN, 1);
    }
    split_kernel<<<(DD * DD) / 256, 256>>>(emb_W2, w2hi, w2lo, DD * DD);
    launch_tf32(u1, DD, DD, nullptr, 0, w2hi, w2lo, DD, h, DD,
                nullptr, 0, emb_b2, nullptr, nullptr, NN, DD, DD, 0);

    for (int l = 0; l < LL; l++) {
        const float* W1l  = msg_W1 + (size_t)l * 272 * HH;
        const float* b1l  = msg_b1 + (size_t)l * HH;
        const float* W2l  = msg_W2 + (size_t)l * HH * DD;
        const float* U1h  = upd_W1 + (size_t)l * 2 * DD * HH;
        const float* U1a  = U1h + (size_t)DD * HH;
        const float* ub1l = upd_b1 + (size_t)l * HH;
        const float* uW2l = upd_W2 + (size_t)l * HH * DD;
        const float* ub2l = upd_b2 + (size_t)l * DD;

        // packs: p1 = split([W1src | W1dst]), bias512 = [0 | b1]
        pack1_split_kernel<<<(DD * 512) / 256, 256>>>(W1l, p1hi, p1lo, b1l, bias512);
        // Bu = [U1h ; W2l @ U1a] fp32, then split
        copyU1h_kernel<<<(DD * HH) / 256, 256>>>(U1h, Bu);
        {
            dim3 gw(HH / 64, HH / 64);
            gemm_f32<<<gw, 256>>>(W2l, DD, U1a, HH, Bu + (size_t)DD * HH, HH,
                                  nullptr, HH, HH, DD, 0);
        }
        split_kernel<<<(384 * HH) / 256, 256>>>(Bu, buhi, bulo, 384 * HH);
        split_kernel<<<(HH * DD) / 256, 256>>>(uW2l, w2hi, w2lo, HH * DD);

        // HsHd = h @ Bpack1 + bias512   (N x 512)
        launch_tf32(h, DD, DD, nullptr, 0, p1hi, p1lo, 512, HsHd, 512,
                    nullptr, 0, bias512, nullptr, nullptr, NN, 512, DD, 0);

        // S[n] = sum over incoming edges of silu(pre)
        edge_agg<<<NN / NPB, HH>>>(HsHd, W1l + (size_t)2 * DD * HH,
                                   ef, dsort, srcs, offs, S);

        // u1 = silu([h|S] @ Bu + ub1 + deg*b2u)
        launch_tf32(h, DD, DD, S, HH, buhi, bulo, HH, u1, HH,
                    nullptr, 0, ub1l, degf, b2u + (size_t)l * HH, NN, HH, 384, 1);

        // h = h + u1 @ uW2 + ub2
        launch_tf32(u1, HH, HH, nullptr, 0, w2hi, w2lo, DD, h, DD,
                    h, DD, ub2l, nullptr, nullptr, NN, DD, HH, 0);
    }

    graph_sum<<<NN / 128, 128>>>(h, batch, gsum, gcnt);
    readout_kernel<<<1, 256>>>(gsum, gcnt, r_W1, r_b1, r_W2, r_b2, out);
    (void)in_sizes; (void)n_in; (void)out_size;
}